// round 11
// baseline (speedup 1.0000x reference)
#include <cuda_runtime.h>

#define NT 512          // threads per CTA (16 warps)
#define TT 48           // encoder timesteps
#define FUT 48          // decoder steps
#define NNODE 32
#define INF 11
#define LDA 68          // normal activation row stride (floats)
#define LDZ 132         // zbuf row stride: [xf(64) | hx(64)] + pad
#define LDGR 260        // padded g row stride (floats)

// ---------------------------------------------------------------------------
// packed fp32x2 carried as b64
// ---------------------------------------------------------------------------
typedef unsigned long long p2;

__device__ __forceinline__ p2 ffma2p(p2 a, p2 b, p2 c) {
  p2 d;
  asm("fma.rn.f32x2 %0, %1, %2, %3;" : "=l"(d) : "l"(a), "l"(b), "l"(c));
  return d;
}
__device__ __forceinline__ p2 pack2(float lo, float hi) {
  p2 d;
  asm("mov.b64 %0, {%1, %2};" : "=l"(d) : "f"(lo), "f"(hi));
  return d;
}
__device__ __forceinline__ float2 up2(p2 a) {
  float2 f;
  asm("mov.b64 {%0, %1}, %2;" : "=f"(f.x), "=f"(f.y) : "l"(a));
  return f;
}
__device__ __forceinline__ float hadd2(p2 a) {
  float2 f = up2(a);
  return f.x + f.y;
}

__device__ __forceinline__ float sigf(float x) {
  return __fdividef(1.0f, 1.0f + __expf(-x));
}
__device__ __forceinline__ float tanh_f(float x) {
  return __fdividef(2.0f, 1.0f + __expf(-2.0f * x)) - 1.0f;
}

struct __align__(16) Smem {
  float Wenc[12][64];      // row 11 zero-padded
  float Wg1[64][64];
  float Wg2[64][64];
  float Wd1[64][32];
  float Wd2[32][8];
  float benc[64];
  float bg1[64];
  float bg2[64];
  float bd1[32];
  float bd2[8];
  float Ahat2[32][68];     // SPLAT pairs of normalized adjacency rows (static)
  float dvec[32];
  float xbufs[2][32][24];  // SPLAT input frame (12 k, k=11 stays zero)
  float act0[2][32][LDA];  // enc / tmp2
  float act1[2][32][LDA];  // tmp
  float zbuf[2][32][LDZ];  // [xf | hx] per row (LSTM z-stream)
  float g[2][32][LDGR];    // LSTM pre-activations
  float h1[2][32][36];     // decoder hidden
};

// ---- epilogue store (normal layout, 4 cols) --------------------------------
__device__ __forceinline__ void st4(float* p, p2 a0, p2 a1, bool relu) {
  float2 f0 = up2(a0), f1 = up2(a1);
  float4 o;
  o.x = relu ? fmaxf(f0.x, 0.f) : f0.x;
  o.y = relu ? fmaxf(f0.y, 0.f) : f0.y;
  o.z = relu ? fmaxf(f1.x, 0.f) : f1.x;
  o.w = relu ? fmaxf(f1.y, 0.f) : f1.y;
  *reinterpret_cast<float4*>(p) = o;
}

// enc GEMM: A = SPLAT xbufs rows (K=12 padded), 4 cols (j in 0..15), both
// batches share weight loads. relu output.
__device__ __forceinline__ void encmm(const float* __restrict__ As0,
                                      const float* __restrict__ As1,
                                      const float* __restrict__ W,
                                      const float* __restrict__ bias,
                                      float* __restrict__ out0,
                                      float* __restrict__ out1, int j) {
  const int ca = 4 * j;
  ulonglong2 b0 = *reinterpret_cast<const ulonglong2*>(bias + ca);
  p2 x0 = b0.x, x1 = b0.y, y0 = b0.x, y1 = b0.y;
#pragma unroll
  for (int t = 0; t < 3; t++) {
    ulonglong2 aA = *reinterpret_cast<const ulonglong2*>(As0 + 8 * t);
    ulonglong2 aB = *reinterpret_cast<const ulonglong2*>(As0 + 8 * t + 4);
    ulonglong2 cA = *reinterpret_cast<const ulonglong2*>(As1 + 8 * t);
    ulonglong2 cB = *reinterpret_cast<const ulonglong2*>(As1 + 8 * t + 4);
    p2 sp0[4] = {aA.x, aA.y, aB.x, aB.y};
    p2 sp1[4] = {cA.x, cA.y, cB.x, cB.y};
#pragma unroll
    for (int q = 0; q < 4; q++) {
      ulonglong2 w0 =
          *reinterpret_cast<const ulonglong2*>(W + (4 * t + q) * 64 + ca);
      x0 = ffma2p(sp0[q], w0.x, x0);
      x1 = ffma2p(sp0[q], w0.y, x1);
      y0 = ffma2p(sp1[q], w0.x, y0);
      y1 = ffma2p(sp1[q], w0.y, y1);
    }
  }
  st4(out0 + ca, x0, x1, true);
  st4(out1 + ca, y0, y1, true);
}

// K=64 GEMM, normal A (float4 loads), 4 cols (j in 0..15), both batches.
template<int LDW, bool BIAS, bool RELU>
__device__ __forceinline__ void rowmm64(const float* __restrict__ A0,
                                        const float* __restrict__ A1,
                                        const float* __restrict__ W,
                                        const float* __restrict__ bias,
                                        float* __restrict__ out0,
                                        float* __restrict__ out1, int j) {
  const int ca = 4 * j;
  p2 x0, x1, y0, y1;
  if (BIAS) {
    ulonglong2 b0 = *reinterpret_cast<const ulonglong2*>(bias + ca);
    x0 = b0.x; x1 = b0.y; y0 = b0.x; y1 = b0.y;
  } else {
    x0 = x1 = y0 = y1 = 0ull;
  }
#pragma unroll
  for (int t = 0; t < 16; t++) {
    float4 a0v = *reinterpret_cast<const float4*>(A0 + 4 * t);
    float4 a1v = *reinterpret_cast<const float4*>(A1 + 4 * t);
    p2 sp0[4] = {pack2(a0v.x, a0v.x), pack2(a0v.y, a0v.y),
                 pack2(a0v.z, a0v.z), pack2(a0v.w, a0v.w)};
    p2 sp1[4] = {pack2(a1v.x, a1v.x), pack2(a1v.y, a1v.y),
                 pack2(a1v.z, a1v.z), pack2(a1v.w, a1v.w)};
#pragma unroll
    for (int q = 0; q < 4; q++) {
      ulonglong2 w0 =
          *reinterpret_cast<const ulonglong2*>(W + (4 * t + q) * LDW + ca);
      x0 = ffma2p(sp0[q], w0.x, x0);
      x1 = ffma2p(sp0[q], w0.y, x1);
      y0 = ffma2p(sp1[q], w0.x, y0);
      y1 = ffma2p(sp1[q], w0.y, y1);
    }
  }
  st4(out0 + ca, x0, x1, RELU);
  st4(out1 + ca, y0, y1, RELU);
}

// decoder h1 GEMM: K=64, 2 cols per thread (j in 0..15 -> cols 2j..2j+1).
__device__ __forceinline__ void d1mm(const float* __restrict__ A0,
                                     const float* __restrict__ A1,
                                     const float* __restrict__ W,   // 64x32
                                     const float* __restrict__ bias,
                                     float* __restrict__ out0,
                                     float* __restrict__ out1, int j) {
  const int c = 2 * j;
  p2 bb = *reinterpret_cast<const p2*>(bias + c);
  p2 x0 = bb, y0 = bb;
#pragma unroll
  for (int t = 0; t < 16; t++) {
    float4 a0v = *reinterpret_cast<const float4*>(A0 + 4 * t);
    float4 a1v = *reinterpret_cast<const float4*>(A1 + 4 * t);
    p2 sp0[4] = {pack2(a0v.x, a0v.x), pack2(a0v.y, a0v.y),
                 pack2(a0v.z, a0v.z), pack2(a0v.w, a0v.w)};
    p2 sp1[4] = {pack2(a1v.x, a1v.x), pack2(a1v.y, a1v.y),
                 pack2(a1v.z, a1v.z), pack2(a1v.w, a1v.w)};
#pragma unroll
    for (int q = 0; q < 4; q++) {
      p2 wv = *reinterpret_cast<const p2*>(W + (4 * t + q) * 32 + c);
      x0 = ffma2p(sp0[q], wv, x0);
      y0 = ffma2p(sp1[q], wv, y0);
    }
  }
  float2 f0 = up2(x0), f1 = up2(y0);
  float2 o0 = make_float2(fmaxf(f0.x, 0.f), fmaxf(f0.y, 0.f));
  float2 o1 = make_float2(fmaxf(f1.x, 0.f), fmaxf(f1.y, 0.f));
  *reinterpret_cast<float2*>(out0 + c) = o0;
  *reinterpret_cast<float2*>(out1 + c) = o1;
}

// Ahat GEMM: A = pre-splatted Ahat2 row (shared by both batches), W0/W1 =
// per-batch dynamic matrices (LDA-strided). K=32, 4 cols, relu output.
__device__ __forceinline__ void ahatmm(const float* __restrict__ A2,
                                       const float* __restrict__ W0,
                                       const float* __restrict__ W1,
                                       const float* __restrict__ bias,
                                       float* __restrict__ out0,
                                       float* __restrict__ out1, int j) {
  const int ca = 4 * j;
  ulonglong2 b0 = *reinterpret_cast<const ulonglong2*>(bias + ca);
  p2 x0 = b0.x, x1 = b0.y, y0 = b0.x, y1 = b0.y;
#pragma unroll
  for (int t = 0; t < 8; t++) {
    ulonglong2 aA = *reinterpret_cast<const ulonglong2*>(A2 + 8 * t);
    ulonglong2 aB = *reinterpret_cast<const ulonglong2*>(A2 + 8 * t + 4);
    p2 sp[4] = {aA.x, aA.y, aB.x, aB.y};
#pragma unroll
    for (int q = 0; q < 4; q++) {
      ulonglong2 wa =
          *reinterpret_cast<const ulonglong2*>(W0 + (4 * t + q) * LDA + ca);
      x0 = ffma2p(sp[q], wa.x, x0);
      x1 = ffma2p(sp[q], wa.y, x1);
      ulonglong2 wc =
          *reinterpret_cast<const ulonglong2*>(W1 + (4 * t + q) * LDA + ca);
      y0 = ffma2p(sp[q], wc.x, y0);
      y1 = ffma2p(sp[q], wc.y, y1);
    }
  }
  st4(out0 + ca, x0, x1, true);
  st4(out1 + ca, y0, y1, true);
}

// Full two-batch step at 512 threads.
// GEMM map: r = tid>>4 (row), j = tid&15 (4-col group); the 16 threads of a
// row live in one half-warp, so row-local edges need only __syncwarp.
// LSTM map: warp w owns cols 16w..16w+15; lane = (rowpar<<4)|(kc<<2)|cg.
// Thread: 4 cols (colbase=16w+4cg) x 32-k quarter (kc), rows 2q+rowpar.
// Row-parity halves hit disjoint bank-quad sets (132 % 32 = 4 word shift).
__device__ __forceinline__ void step2(Smem& s, const p2 wk[4][16],
                                      const float4& bb4, const int* zoff,
                                      float4& cxa, float4& cxb,
                                      int tid, int colbase, int lane,
                                      int rowpar) {
  const int r = tid >> 4;
  const int j = tid & 15;

  // enc = relu(x @ W_enc + b_enc) -> act0               (row-local consumer)
  encmm(&s.xbufs[0][r][0], &s.xbufs[1][r][0], &s.Wenc[0][0], s.benc,
        &s.act0[0][r][0], &s.act0[1][r][0], j);
  __syncwarp();
  // tmp = enc @ W_g1 -> act1                            (all-to-all consumer)
  rowmm64<64, false, false>(&s.act0[0][r][0], &s.act0[1][r][0], &s.Wg1[0][0],
                            nullptr, &s.act1[0][r][0], &s.act1[1][r][0], j);
  __syncthreads();
  // s1 = relu(Ahat @ tmp + b_g1) -> zbuf[0..64)         (row-local consumer)
  ahatmm(&s.Ahat2[r][0], &s.act1[0][0][0], &s.act1[1][0][0], s.bg1,
         &s.zbuf[0][r][0], &s.zbuf[1][r][0], j);
  __syncwarp();
  // tmp2 = s1 @ W_g2 -> act0                            (all-to-all consumer)
  rowmm64<64, false, false>(&s.zbuf[0][r][0], &s.zbuf[1][r][0], &s.Wg2[0][0],
                            nullptr, &s.act0[0][r][0], &s.act0[1][r][0], j);
  __syncthreads();
  // xf = relu(Ahat @ tmp2 + b_g2) -> zbuf[0..64)        (LSTM z-stream)
  ahatmm(&s.Ahat2[r][0], &s.act0[0][0][0], &s.act0[1][0][0], s.bg2,
         &s.zbuf[0][r][0], &s.zbuf[1][r][0], j);
  __syncthreads();

  // LSTM both batches: g[bat][row][c] = bias + z[bat][row] . W[:,c]
#pragma unroll 2
  for (int q = 0; q < 16; q++) {
    const int rr = 2 * q + rowpar;
    const float* zr0 = &s.zbuf[0][rr][0];
    const float* zr1 = &s.zbuf[1][rr][0];
    p2 a0 = 0ull, a1 = 0ull, a2 = 0ull, a3 = 0ull;
    p2 e0 = 0ull, e1 = 0ull, e2 = 0ull, e3 = 0ull;
#pragma unroll
    for (int i = 0; i < 8; i++) {
      ulonglong2 z0 = *reinterpret_cast<const ulonglong2*>(zr0 + zoff[i]);
      ulonglong2 z1 = *reinterpret_cast<const ulonglong2*>(zr1 + zoff[i]);
      p2 wlo0 = wk[0][2 * i], whi0 = wk[0][2 * i + 1];
      p2 wlo1 = wk[1][2 * i], whi1 = wk[1][2 * i + 1];
      p2 wlo2 = wk[2][2 * i], whi2 = wk[2][2 * i + 1];
      p2 wlo3 = wk[3][2 * i], whi3 = wk[3][2 * i + 1];
      a0 = ffma2p(z0.x, wlo0, a0); a0 = ffma2p(z0.y, whi0, a0);
      a1 = ffma2p(z0.x, wlo1, a1); a1 = ffma2p(z0.y, whi1, a1);
      a2 = ffma2p(z0.x, wlo2, a2); a2 = ffma2p(z0.y, whi2, a2);
      a3 = ffma2p(z0.x, wlo3, a3); a3 = ffma2p(z0.y, whi3, a3);
      e0 = ffma2p(z1.x, wlo0, e0); e0 = ffma2p(z1.y, whi0, e0);
      e1 = ffma2p(z1.x, wlo1, e1); e1 = ffma2p(z1.y, whi1, e1);
      e2 = ffma2p(z1.x, wlo2, e2); e2 = ffma2p(z1.y, whi2, e2);
      e3 = ffma2p(z1.x, wlo3, e3); e3 = ffma2p(z1.y, whi3, e3);
    }
    float s0 = hadd2(a0), s1v = hadd2(a1), s2 = hadd2(a2), s3 = hadd2(a3);
    float t0 = hadd2(e0), t1 = hadd2(e1), t2 = hadd2(e2), t3 = hadd2(e3);
    s0 += __shfl_xor_sync(0xffffffffu, s0, 4);
    s1v += __shfl_xor_sync(0xffffffffu, s1v, 4);
    s2 += __shfl_xor_sync(0xffffffffu, s2, 4);
    s3 += __shfl_xor_sync(0xffffffffu, s3, 4);
    t0 += __shfl_xor_sync(0xffffffffu, t0, 4);
    t1 += __shfl_xor_sync(0xffffffffu, t1, 4);
    t2 += __shfl_xor_sync(0xffffffffu, t2, 4);
    t3 += __shfl_xor_sync(0xffffffffu, t3, 4);
    s0 += __shfl_xor_sync(0xffffffffu, s0, 8);
    s1v += __shfl_xor_sync(0xffffffffu, s1v, 8);
    s2 += __shfl_xor_sync(0xffffffffu, s2, 8);
    s3 += __shfl_xor_sync(0xffffffffu, s3, 8);
    t0 += __shfl_xor_sync(0xffffffffu, t0, 8);
    t1 += __shfl_xor_sync(0xffffffffu, t1, 8);
    t2 += __shfl_xor_sync(0xffffffffu, t2, 8);
    t3 += __shfl_xor_sync(0xffffffffu, t3, 8);
    if ((lane & 12) == 0) {   // kc == 0 lanes store
      float4 o0, o1;
      o0.x = s0 + bb4.x; o0.y = s1v + bb4.y;
      o0.z = s2 + bb4.z; o0.w = s3 + bb4.w;
      o1.x = t0 + bb4.x; o1.y = t1 + bb4.y;
      o1.z = t2 + bb4.z; o1.w = t3 + bb4.w;
      *reinterpret_cast<float4*>(&s.g[0][rr][colbase]) = o0;
      *reinterpret_cast<float4*>(&s.g[1][rr][colbase]) = o1;
    }
  }
  __syncthreads();

  // gate nonlinearity + state update; hx -> zbuf[64+base]
  {
    const int base = 4 * j;
#pragma unroll
    for (int bat = 0; bat < 2; bat++) {
      float4 gi = *reinterpret_cast<const float4*>(&s.g[bat][r][base]);
      float4 gf = *reinterpret_cast<const float4*>(&s.g[bat][r][64 + base]);
      float4 gg = *reinterpret_cast<const float4*>(&s.g[bat][r][128 + base]);
      float4 go = *reinterpret_cast<const float4*>(&s.g[bat][r][192 + base]);
      float4 cc = bat ? cxb : cxa;
      float4 cn, hn;
      cn.x = sigf(gf.x) * cc.x + sigf(gi.x) * tanh_f(gg.x);
      cn.y = sigf(gf.y) * cc.y + sigf(gi.y) * tanh_f(gg.y);
      cn.z = sigf(gf.z) * cc.z + sigf(gi.z) * tanh_f(gg.z);
      cn.w = sigf(gf.w) * cc.w + sigf(gi.w) * tanh_f(gg.w);
      hn.x = sigf(go.x) * tanh_f(cn.x);
      hn.y = sigf(go.y) * tanh_f(cn.y);
      hn.z = sigf(go.z) * tanh_f(cn.z);
      hn.w = sigf(go.w) * tanh_f(cn.w);
      if (bat) cxb = cn; else cxa = cn;
      *reinterpret_cast<float4*>(&s.zbuf[bat][r][64 + base]) = hn;
    }
  }
  __syncwarp();
}

__global__ void __launch_bounds__(NT, 1)
stgnn_kernel(const float* __restrict__ x, const float* __restrict__ adj,
             const float* __restrict__ Wenc_g, const float* __restrict__ benc_g,
             const float* __restrict__ Wg1_g, const float* __restrict__ bg1_g,
             const float* __restrict__ Wg2_g, const float* __restrict__ bg2_g,
             const float* __restrict__ Wih_g, const float* __restrict__ Whh_g,
             const float* __restrict__ bih_g, const float* __restrict__ bhh_g,
             const float* __restrict__ Wd1_g, const float* __restrict__ bd1_g,
             const float* __restrict__ Wd2_g, const float* __restrict__ bd2_g,
             float* __restrict__ out, int B) {
  extern __shared__ __align__(16) unsigned char smem_raw[];
  Smem& s = *reinterpret_cast<Smem*>(smem_raw);
  const int tid = threadIdx.x;
  const int b0 = 2 * blockIdx.x;
  const int b1 = min(b0 + 1, B - 1);   // clamp for odd B (duplicate work)
  const int r = tid >> 4;
  const int j = tid & 15;
  const int w = tid >> 5;
  const int lane = tid & 31;
  const int rowpar = lane >> 4;
  const int kc = (lane >> 2) & 3;
  const int cg = lane & 3;
  const int colbase = 16 * w + 4 * cg;

  // ---- one-time per-CTA setup ----
  for (int i = tid; i < 12 * 64; i += NT) {
    int k = i >> 6, c = i & 63;
    (&s.Wenc[0][0])[i] = (k < INF) ? Wenc_g[k * 64 + c] : 0.f;
  }
  for (int i = tid; i < 64 * 64; i += NT) (&s.Wg1[0][0])[i] = Wg1_g[i];
  for (int i = tid; i < 64 * 64; i += NT) (&s.Wg2[0][0])[i] = Wg2_g[i];
  for (int i = tid; i < 64 * 32; i += NT) (&s.Wd1[0][0])[i] = Wd1_g[i];
  if (tid < 192) s.Wd2[tid / 6][tid % 6] = Wd2_g[tid];
  if (tid < 64) {
    s.benc[tid] = benc_g[tid];
    s.bg1[tid] = bg1_g[tid];
    s.bg2[tid] = bg2_g[tid];
  }
  if (tid < 32) s.bd1[tid] = bd1_g[tid];
  if (tid < 6) s.bd2[tid] = bd2_g[tid];
  if (tid < 32) {
    float sum = 0.f;
    for (int jj = 0; jj < 32; jj++)
      sum += (jj == tid) ? 1.f : adj[tid * 32 + jj];
    s.dvec[tid] = rsqrtf(fmaxf(sum, 1.f));
  }
  for (int i = tid; i < 2 * 32 * LDZ; i += NT) (&s.zbuf[0][0][0])[i] = 0.f;
  for (int i = tid; i < 2 * 32 * 24; i += NT) (&s.xbufs[0][0][0])[i] = 0.f;
  __syncthreads();
  for (int i = tid; i < 32 * 32; i += NT) {
    int ii = i >> 5, jj = i & 31;
    float a = (ii == jj) ? 1.f : adj[i];
    float v = s.dvec[ii] * a * s.dvec[jj];
    s.Ahat2[ii][2 * jj] = v;
    s.Ahat2[ii][2 * jj + 1] = v;
  }

  // LSTM weights: 4 cols x 32-k quarter (rotation baked in), shared by both
  // batches. Full k-vector for col c: k<64 -> W_ih[c][k], else W_hh[c][k-64].
  p2 wk[4][16];
  float4 bb4;
  int zoff[8];
#pragma unroll
  for (int i = 0; i < 8; i++) {
    int lc = (i + 2 * kc) & 7;
    zoff[i] = kc * 32 + lc * 4;
  }
  {
    const float* base =
        (kc < 2) ? (Wih_g + (size_t)kc * 32) : (Whh_g + (size_t)(kc - 2) * 32);
    float bbv[4];
#pragma unroll
    for (int cc = 0; cc < 4; cc++) {
      int c = colbase + cc;
      bbv[cc] = bih_g[c] + bhh_g[c];
      const float* src = base + (size_t)c * 64;
#pragma unroll
      for (int i = 0; i < 8; i++) {
        int lc = (i + 2 * kc) & 7;
        wk[cc][2 * i]     = pack2(src[lc * 4],     src[lc * 4 + 1]);
        wk[cc][2 * i + 1] = pack2(src[lc * 4 + 2], src[lc * 4 + 3]);
      }
    }
    bb4 = make_float4(bbv[0], bbv[1], bbv[2], bbv[3]);
  }
  float4 cxa = make_float4(0.f, 0.f, 0.f, 0.f);
  float4 cxb = cxa;
  __syncthreads();

  // ---- encoder: 48 steps ----
  for (int t = 0; t < TT; t++) {
    const float* xt0 = x + ((size_t)b0 * TT + t) * (NNODE * INF);
    const float* xt1 = x + ((size_t)b1 * TT + t) * (NNODE * INF);
    if (j < INF) {
      float v0 = xt0[r * INF + j];
      float v1 = xt1[r * INF + j];
      *reinterpret_cast<p2*>(&s.xbufs[0][r][2 * j]) = pack2(v0, v0);
      *reinterpret_cast<p2*>(&s.xbufs[1][r][2 * j]) = pack2(v1, v1);
    }
    __syncwarp();
    step2(s, wk, bb4, zoff, cxa, cxb, tid, colbase, lane, rowpar);
  }

  // ---- decoder: 48 steps ----
  for (int f = 0; f < FUT; f++) {
    step2(s, wk, bb4, zoff, cxa, cxb, tid, colbase, lane, rowpar);
    // h1 = relu(hx @ W_d1 + b_d1); hx row-local in zbuf[bat][r][64..128)
    d1mm(&s.zbuf[0][r][64], &s.zbuf[1][r][64], &s.Wd1[0][0], s.bd1,
         &s.h1[0][r][0], &s.h1[1][r][0], j);
    __syncthreads();
    // res = h1 @ W_d2 + b_d2 ; pred += res ; emit (both batches)
    if (tid < 192) {
      int rr = tid / 6, d = tid - rr * 6;
      float acc0 = s.bd2[d], acc1 = s.bd2[d];
#pragma unroll
      for (int k = 0; k < 32; k++) {
        float wv = s.Wd2[k][d];
        acc0 += s.h1[0][rr][k] * wv;
        acc1 += s.h1[1][rr][k] * wv;
      }
      float p0 = s.xbufs[0][rr][2 * d] + acc0;
      float p1 = s.xbufs[1][rr][2 * d] + acc1;
      *reinterpret_cast<p2*>(&s.xbufs[0][rr][2 * d]) = pack2(p0, p0);
      *reinterpret_cast<p2*>(&s.xbufs[1][rr][2 * d]) = pack2(p1, p1);
      out[(((size_t)b0 * FUT + f) * NNODE + rr) * 6 + d] = p0;
      out[(((size_t)b1 * FUT + f) * NNODE + rr) * 6 + d] = p1;
    }
    __syncthreads();
  }
}

extern "C" void kernel_launch(void* const* d_in, const int* in_sizes, int n_in,
                              void* d_out, int out_size) {
  const float* x    = (const float*)d_in[0];
  const float* adj  = (const float*)d_in[1];
  const float* Wenc = (const float*)d_in[2];
  const float* benc = (const float*)d_in[3];
  const float* Wg1  = (const float*)d_in[4];
  const float* bg1  = (const float*)d_in[5];
  const float* Wg2  = (const float*)d_in[6];
  const float* bg2  = (const float*)d_in[7];
  const float* Wih  = (const float*)d_in[8];
  const float* Whh  = (const float*)d_in[9];
  const float* bih  = (const float*)d_in[10];
  const float* bhh  = (const float*)d_in[11];
  const float* Wd1  = (const float*)d_in[12];
  const float* bd1  = (const float*)d_in[13];
  const float* Wd2  = (const float*)d_in[14];
  const float* bd2  = (const float*)d_in[15];
  float* out = (float*)d_out;

  int B = in_sizes[0] / (TT * NNODE * INF);
  int nblk = (B + 1) / 2;

  cudaFuncSetAttribute(stgnn_kernel,
                       cudaFuncAttributeMaxDynamicSharedMemorySize,
                       (int)sizeof(Smem));
  stgnn_kernel<<<nblk, NT, sizeof(Smem)>>>(x, adj, Wenc, benc, Wg1, bg1, Wg2,
                                           bg2, Wih, Whh, bih, bhh, Wd1, bd1,
                                           Wd2, bd2, out, B);
}

// round 14
// speedup vs baseline: 1.0816x; 1.0816x over previous
#include <cuda_runtime.h>

#define NT 512          // threads per CTA (16 warps)
#define TT 48
#define FUT 48
#define NNODE 32
#define INF 11
#define LDA 68          // normal activation row stride (floats)
#define LDZ 132         // zbuf row stride: [xf(64) | hx(64)] + pad
#define LDGR 260        // padded g row stride (floats)

typedef unsigned long long p2;

__device__ __forceinline__ p2 ffma2p(p2 a, p2 b, p2 c) {
  p2 d;
  asm("fma.rn.f32x2 %0, %1, %2, %3;" : "=l"(d) : "l"(a), "l"(b), "l"(c));
  return d;
}
__device__ __forceinline__ p2 pack2(float lo, float hi) {
  p2 d;
  asm("mov.b64 %0, {%1, %2};" : "=l"(d) : "f"(lo), "f"(hi));
  return d;
}
__device__ __forceinline__ float2 up2(p2 a) {
  float2 f;
  asm("mov.b64 {%0, %1}, %2;" : "=f"(f.x), "=f"(f.y) : "l"(a));
  return f;
}
__device__ __forceinline__ float hadd2(p2 a) {
  float2 f = up2(a);
  return f.x + f.y;
}

__device__ __forceinline__ float sigf(float x) {
  return __fdividef(1.0f, 1.0f + __expf(-x));
}
__device__ __forceinline__ float tanh_f(float x) {
  return __fdividef(2.0f, 1.0f + __expf(-2.0f * x)) - 1.0f;
}

struct __align__(16) Smem {
  float Wenc[12][64];      // row 11 zero-padded
  float Wg1[64][64];
  float Wg2[64][64];
  float Wd1[64][32];
  float Wd2[32][8];
  float benc[64];
  float bg1[64];
  float bg2[64];
  float bd1[32];
  float bd2[8];
  float Ahat2[32][68];     // SPLAT pairs of normalized adjacency rows
  float dvec[32];
  float xbufs[2][32][24];  // SPLAT input frame (12 k, k=11 stays zero)
  float act0[2][32][LDA];  // enc / tmp2
  float act1[2][32][LDA];  // tmp
  float zbuf[2][32][LDZ];  // [xf | hx] per row (LSTM z-stream)
  float g[2][32][LDGR];    // LSTM pre-activations
  float h1[2][32][36];     // decoder hidden
};

__device__ __forceinline__ void st4(float* p, p2 a0, p2 a1, bool relu) {
  float2 f0 = up2(a0), f1 = up2(a1);
  float4 o;
  o.x = relu ? fmaxf(f0.x, 0.f) : f0.x;
  o.y = relu ? fmaxf(f0.y, 0.f) : f0.y;
  o.z = relu ? fmaxf(f1.x, 0.f) : f1.x;
  o.w = relu ? fmaxf(f1.y, 0.f) : f1.y;
  *reinterpret_cast<float4*>(p) = o;
}

// enc GEMM: A = SPLAT xbufs row (K=12 padded). 4 output cols at ca.
__device__ __forceinline__ void encmm(const float* __restrict__ As0,
                                      const float* __restrict__ As1,
                                      const float* __restrict__ W,
                                      const float* __restrict__ bias,
                                      float* __restrict__ out0,
                                      float* __restrict__ out1, int ca) {
  ulonglong2 b0 = *reinterpret_cast<const ulonglong2*>(bias + ca);
  p2 x0 = b0.x, x1 = b0.y, y0 = b0.x, y1 = b0.y;
#pragma unroll
  for (int t = 0; t < 3; t++) {
    ulonglong2 aA = *reinterpret_cast<const ulonglong2*>(As0 + 8 * t);
    ulonglong2 aB = *reinterpret_cast<const ulonglong2*>(As0 + 8 * t + 4);
    ulonglong2 cA = *reinterpret_cast<const ulonglong2*>(As1 + 8 * t);
    ulonglong2 cB = *reinterpret_cast<const ulonglong2*>(As1 + 8 * t + 4);
    p2 sp0[4] = {aA.x, aA.y, aB.x, aB.y};
    p2 sp1[4] = {cA.x, cA.y, cB.x, cB.y};
#pragma unroll
    for (int q = 0; q < 4; q++) {
      ulonglong2 w0 =
          *reinterpret_cast<const ulonglong2*>(W + (4 * t + q) * 64 + ca);
      x0 = ffma2p(sp0[q], w0.x, x0);
      x1 = ffma2p(sp0[q], w0.y, x1);
      y0 = ffma2p(sp1[q], w0.x, y0);
      y1 = ffma2p(sp1[q], w0.y, y1);
    }
  }
  st4(out0 + ca, x0, x1, true);
  st4(out1 + ca, y0, y1, true);
}

// K=64 GEMM, normal A (float4 loads), 4 cols at ca, both batches.
template<int LDW, bool BIAS, bool RELU>
__device__ __forceinline__ void rowmm64(const float* __restrict__ A0,
                                        const float* __restrict__ A1,
                                        const float* __restrict__ W,
                                        const float* __restrict__ bias,
                                        float* __restrict__ out0,
                                        float* __restrict__ out1, int ca) {
  p2 x0, x1, y0, y1;
  if (BIAS) {
    ulonglong2 b0 = *reinterpret_cast<const ulonglong2*>(bias + ca);
    x0 = b0.x; x1 = b0.y; y0 = b0.x; y1 = b0.y;
  } else {
    x0 = x1 = y0 = y1 = 0ull;
  }
#pragma unroll
  for (int t = 0; t < 16; t++) {
    float4 a0v = *reinterpret_cast<const float4*>(A0 + 4 * t);
    float4 a1v = *reinterpret_cast<const float4*>(A1 + 4 * t);
    p2 sp0[4] = {pack2(a0v.x, a0v.x), pack2(a0v.y, a0v.y),
                 pack2(a0v.z, a0v.z), pack2(a0v.w, a0v.w)};
    p2 sp1[4] = {pack2(a1v.x, a1v.x), pack2(a1v.y, a1v.y),
                 pack2(a1v.z, a1v.z), pack2(a1v.w, a1v.w)};
#pragma unroll
    for (int q = 0; q < 4; q++) {
      ulonglong2 w0 =
          *reinterpret_cast<const ulonglong2*>(W + (4 * t + q) * LDW + ca);
      x0 = ffma2p(sp0[q], w0.x, x0);
      x1 = ffma2p(sp0[q], w0.y, x1);
      y0 = ffma2p(sp1[q], w0.x, y0);
      y1 = ffma2p(sp1[q], w0.y, y1);
    }
  }
  st4(out0 + ca, x0, x1, RELU);
  st4(out1 + ca, y0, y1, RELU);
}

// Ahat GEMM: A = pre-splatted Ahat2 row, W0/W1 per-batch (LDA-strided), K=32.
__device__ __forceinline__ void ahatmm(const float* __restrict__ A2,
                                       const float* __restrict__ W0,
                                       const float* __restrict__ W1,
                                       const float* __restrict__ bias,
                                       float* __restrict__ out0,
                                       float* __restrict__ out1, int ca) {
  ulonglong2 b0 = *reinterpret_cast<const ulonglong2*>(bias + ca);
  p2 x0 = b0.x, x1 = b0.y, y0 = b0.x, y1 = b0.y;
#pragma unroll
  for (int t = 0; t < 8; t++) {
    ulonglong2 aA = *reinterpret_cast<const ulonglong2*>(A2 + 8 * t);
    ulonglong2 aB = *reinterpret_cast<const ulonglong2*>(A2 + 8 * t + 4);
    p2 sp[4] = {aA.x, aA.y, aB.x, aB.y};
#pragma unroll
    for (int q = 0; q < 4; q++) {
      ulonglong2 wa =
          *reinterpret_cast<const ulonglong2*>(W0 + (4 * t + q) * LDA + ca);
      x0 = ffma2p(sp[q], wa.x, x0);
      x1 = ffma2p(sp[q], wa.y, x1);
      ulonglong2 wc =
          *reinterpret_cast<const ulonglong2*>(W1 + (4 * t + q) * LDA + ca);
      y0 = ffma2p(sp[q], wc.x, y0);
      y1 = ffma2p(sp[q], wc.y, y1);
    }
  }
  st4(out0 + ca, x0, x1, true);
  st4(out1 + ca, y0, y1, true);
}

// decoder h1 GEMM: one batch per thread (batch = half). 4 cols at ca2.
__device__ __forceinline__ void d1mm(const float* __restrict__ A,
                                     const float* __restrict__ W,   // 64x32
                                     const float* __restrict__ bias,
                                     float* __restrict__ outp, int ca2) {
  ulonglong2 b0 = *reinterpret_cast<const ulonglong2*>(bias + ca2);
  p2 x0 = b0.x, x1 = b0.y;
#pragma unroll
  for (int t = 0; t < 16; t++) {
    float4 av = *reinterpret_cast<const float4*>(A + 4 * t);
    p2 sp[4] = {pack2(av.x, av.x), pack2(av.y, av.y),
                pack2(av.z, av.z), pack2(av.w, av.w)};
#pragma unroll
    for (int q = 0; q < 4; q++) {
      ulonglong2 wv =
          *reinterpret_cast<const ulonglong2*>(W + (4 * t + q) * 32 + ca2);
      x0 = ffma2p(sp[q], wv.x, x0);
      x1 = ffma2p(sp[q], wv.y, x1);
    }
  }
  st4(outp + ca2, x0, x1, true);
}

// Full two-batch step at 512 threads.
// GEMM map: half=tid>>8, r=(tid>>3)&31, j8=tid&7, ca=32*half+4*j8.
// Gate map (FIXED): batch = half, cols {4*j8, 32+4*j8} (h4 loop) -> each
// thread owns 8 gate values; both batches x all 64 cols covered.
// LSTM map: warp w owns cols [16w..16w+16); lane: kc=lane>>2 (16-k eighth),
// cg=lane&3 (col quad colbase=16w+4cg). wk[4][8] = 64 regs.
__device__ __forceinline__ void step2(Smem& s, const p2 wk[4][8],
                                      const float4& bb4, const int* zoff,
                                      float4& cx0, float4& cx1,
                                      int half, int r, int j8, int ca,
                                      int colbase, int lane) {
  // enc = relu(x @ W_enc + b_enc) -> act0
  encmm(&s.xbufs[0][r][0], &s.xbufs[1][r][0], &s.Wenc[0][0], s.benc,
        &s.act0[0][r][0], &s.act0[1][r][0], ca);
  __syncthreads();
  // tmp = enc @ W_g1 -> act1
  rowmm64<64, false, false>(&s.act0[0][r][0], &s.act0[1][r][0], &s.Wg1[0][0],
                            nullptr, &s.act1[0][r][0], &s.act1[1][r][0], ca);
  __syncthreads();
  // s1 = relu(Ahat @ tmp + b_g1) -> zbuf[0..64)
  ahatmm(&s.Ahat2[r][0], &s.act1[0][0][0], &s.act1[1][0][0], s.bg1,
         &s.zbuf[0][r][0], &s.zbuf[1][r][0], ca);
  __syncthreads();
  // tmp2 = s1 @ W_g2 -> act0
  rowmm64<64, false, false>(&s.zbuf[0][r][0], &s.zbuf[1][r][0], &s.Wg2[0][0],
                            nullptr, &s.act0[0][r][0], &s.act0[1][r][0], ca);
  __syncthreads();
  // xf = relu(Ahat @ tmp2 + b_g2) -> zbuf[0..64)  (LSTM z-stream)
  ahatmm(&s.Ahat2[r][0], &s.act0[0][0][0], &s.act0[1][0][0], s.bg2,
         &s.zbuf[0][r][0], &s.zbuf[1][r][0], ca);
  __syncthreads();

  // LSTM: g[bat][row][c] = bias + z[bat][row] . W[:,c], k-split 8 ways.
#pragma unroll 2
  for (int rr = 0; rr < 32; rr++) {
    const float* zr0 = &s.zbuf[0][rr][0];
    const float* zr1 = &s.zbuf[1][rr][0];
    p2 a0 = 0ull, a1 = 0ull, a2 = 0ull, a3 = 0ull;
    p2 e0 = 0ull, e1 = 0ull, e2 = 0ull, e3 = 0ull;
#pragma unroll
    for (int i = 0; i < 4; i++) {
      ulonglong2 z0 = *reinterpret_cast<const ulonglong2*>(zr0 + zoff[i]);
      ulonglong2 z1 = *reinterpret_cast<const ulonglong2*>(zr1 + zoff[i]);
      p2 w0 = wk[0][2 * i], w0h = wk[0][2 * i + 1];
      p2 w1 = wk[1][2 * i], w1h = wk[1][2 * i + 1];
      p2 w2 = wk[2][2 * i], w2h = wk[2][2 * i + 1];
      p2 w3 = wk[3][2 * i], w3h = wk[3][2 * i + 1];
      a0 = ffma2p(z0.x, w0, a0); a0 = ffma2p(z0.y, w0h, a0);
      a1 = ffma2p(z0.x, w1, a1); a1 = ffma2p(z0.y, w1h, a1);
      a2 = ffma2p(z0.x, w2, a2); a2 = ffma2p(z0.y, w2h, a2);
      a3 = ffma2p(z0.x, w3, a3); a3 = ffma2p(z0.y, w3h, a3);
      e0 = ffma2p(z1.x, w0, e0); e0 = ffma2p(z1.y, w0h, e0);
      e1 = ffma2p(z1.x, w1, e1); e1 = ffma2p(z1.y, w1h, e1);
      e2 = ffma2p(z1.x, w2, e2); e2 = ffma2p(z1.y, w2h, e2);
      e3 = ffma2p(z1.x, w3, e3); e3 = ffma2p(z1.y, w3h, e3);
    }
    float s0 = hadd2(a0), s1v = hadd2(a1), s2 = hadd2(a2), s3 = hadd2(a3);
    float t0 = hadd2(e0), t1 = hadd2(e1), t2 = hadd2(e2), t3 = hadd2(e3);
#pragma unroll
    for (int m = 4; m <= 16; m <<= 1) {
      s0 += __shfl_xor_sync(0xffffffffu, s0, m);
      s1v += __shfl_xor_sync(0xffffffffu, s1v, m);
      s2 += __shfl_xor_sync(0xffffffffu, s2, m);
      s3 += __shfl_xor_sync(0xffffffffu, s3, m);
      t0 += __shfl_xor_sync(0xffffffffu, t0, m);
      t1 += __shfl_xor_sync(0xffffffffu, t1, m);
      t2 += __shfl_xor_sync(0xffffffffu, t2, m);
      t3 += __shfl_xor_sync(0xffffffffu, t3, m);
    }
    if (lane < 4) {   // kc == 0 lanes store
      float4 o0, o1;
      o0.x = s0 + bb4.x; o0.y = s1v + bb4.y;
      o0.z = s2 + bb4.z; o0.w = s3 + bb4.w;
      o1.x = t0 + bb4.x; o1.y = t1 + bb4.y;
      o1.z = t2 + bb4.z; o1.w = t3 + bb4.w;
      *reinterpret_cast<float4*>(&s.g[0][rr][colbase]) = o0;
      *reinterpret_cast<float4*>(&s.g[1][rr][colbase]) = o1;
    }
  }
  __syncthreads();

  // gate nonlinearity + state update: batch = half, cols {4j8, 32+4j8}
#pragma unroll
  for (int h4 = 0; h4 < 2; h4++) {
    const int base = 32 * h4 + 4 * j8;
    float4 gi = *reinterpret_cast<const float4*>(&s.g[half][r][base]);
    float4 gf = *reinterpret_cast<const float4*>(&s.g[half][r][64 + base]);
    float4 gg = *reinterpret_cast<const float4*>(&s.g[half][r][128 + base]);
    float4 go = *reinterpret_cast<const float4*>(&s.g[half][r][192 + base]);
    float4 cc = h4 ? cx1 : cx0;
    float4 cn, hn;
    cn.x = sigf(gf.x) * cc.x + sigf(gi.x) * tanh_f(gg.x);
    cn.y = sigf(gf.y) * cc.y + sigf(gi.y) * tanh_f(gg.y);
    cn.z = sigf(gf.z) * cc.z + sigf(gi.z) * tanh_f(gg.z);
    cn.w = sigf(gf.w) * cc.w + sigf(gi.w) * tanh_f(gg.w);
    hn.x = sigf(go.x) * tanh_f(cn.x);
    hn.y = sigf(go.y) * tanh_f(cn.y);
    hn.z = sigf(go.z) * tanh_f(cn.z);
    hn.w = sigf(go.w) * tanh_f(cn.w);
    if (h4) cx1 = cn; else cx0 = cn;
    *reinterpret_cast<float4*>(&s.zbuf[half][r][64 + base]) = hn;
  }
  __syncthreads();
}

__global__ void __launch_bounds__(NT, 1)
stgnn_kernel(const float* __restrict__ x, const float* __restrict__ adj,
             const float* __restrict__ Wenc_g, const float* __restrict__ benc_g,
             const float* __restrict__ Wg1_g, const float* __restrict__ bg1_g,
             const float* __restrict__ Wg2_g, const float* __restrict__ bg2_g,
             const float* __restrict__ Wih_g, const float* __restrict__ Whh_g,
             const float* __restrict__ bih_g, const float* __restrict__ bhh_g,
             const float* __restrict__ Wd1_g, const float* __restrict__ bd1_g,
             const float* __restrict__ Wd2_g, const float* __restrict__ bd2_g,
             float* __restrict__ out, int B) {
  extern __shared__ __align__(16) unsigned char smem_raw[];
  Smem& s = *reinterpret_cast<Smem*>(smem_raw);
  const int tid = threadIdx.x;
  const int b0 = 2 * blockIdx.x;
  const int b1 = min(b0 + 1, B - 1);   // clamp for odd B
  const int half = tid >> 8;           // GEMM col half / gate batch
  const int r = (tid >> 3) & 31;       // row
  const int j8 = tid & 7;
  const int ca = 32 * half + 4 * j8;   // GEMM 4-col base (0..63)
  const int w = tid >> 5;
  const int lane = tid & 31;
  const int kc = lane >> 2;            // LSTM: 16-k eighth (0..7)
  const int cg = lane & 3;
  const int colbase = 16 * w + 4 * cg; // LSTM: gate-col quad (0..255)

  // ---- one-time per-CTA setup ----
  for (int i = tid; i < 12 * 64; i += NT) {
    int k = i >> 6, c = i & 63;
    (&s.Wenc[0][0])[i] = (k < INF) ? Wenc_g[k * 64 + c] : 0.f;
  }
  for (int i = tid; i < 64 * 64; i += NT) (&s.Wg1[0][0])[i] = Wg1_g[i];
  for (int i = tid; i < 64 * 64; i += NT) (&s.Wg2[0][0])[i] = Wg2_g[i];
  for (int i = tid; i < 64 * 32; i += NT) (&s.Wd1[0][0])[i] = Wd1_g[i];
  if (tid < 192) s.Wd2[tid / 6][tid % 6] = Wd2_g[tid];
  if (tid < 64) {
    s.benc[tid] = benc_g[tid];
    s.bg1[tid] = bg1_g[tid];
    s.bg2[tid] = bg2_g[tid];
  }
  if (tid < 32) s.bd1[tid] = bd1_g[tid];
  if (tid < 6) s.bd2[tid] = bd2_g[tid];
  if (tid < 32) {
    float sum = 0.f;
    for (int jj = 0; jj < 32; jj++)
      sum += (jj == tid) ? 1.f : adj[tid * 32 + jj];
    s.dvec[tid] = rsqrtf(fmaxf(sum, 1.f));
  }
  for (int i = tid; i < 2 * 32 * LDZ; i += NT) (&s.zbuf[0][0][0])[i] = 0.f;
  for (int i = tid; i < 2 * 32 * 24; i += NT) (&s.xbufs[0][0][0])[i] = 0.f;
  __syncthreads();
  for (int i = tid; i < 32 * 32; i += NT) {
    int ii = i >> 5, jj = i & 31;
    float a = (ii == jj) ? 1.f : adj[i];
    float v = s.dvec[ii] * a * s.dvec[jj];
    s.Ahat2[ii][2 * jj] = v;
    s.Ahat2[ii][2 * jj + 1] = v;
  }

  // LSTM weights: 4 cols x 16-k eighth. Full k-vector for col c:
  // k<64 -> W_ih[c][k], else W_hh[c][k-64]. Rotation lc=(i+(kc>>1))&3 makes
  // the 8 kc-groups' z-loads conflict-free per instruction.
  p2 wk[4][8];
  float4 bb4;
  int zoff[4];
#pragma unroll
  for (int i = 0; i < 4; i++) {
    int lc = (i + (kc >> 1)) & 3;
    zoff[i] = kc * 16 + lc * 4;
  }
  {
    const float* base =
        (kc < 4) ? (Wih_g + (size_t)kc * 16) : (Whh_g + (size_t)(kc - 4) * 16);
    float bbv[4];
#pragma unroll
    for (int cc = 0; cc < 4; cc++) {
      int c = colbase + cc;
      bbv[cc] = bih_g[c] + bhh_g[c];
      const float* src = base + (size_t)c * 64;
#pragma unroll
      for (int i = 0; i < 4; i++) {
        int lc = (i + (kc >> 1)) & 3;
        wk[cc][2 * i]     = pack2(src[lc * 4],     src[lc * 4 + 1]);
        wk[cc][2 * i + 1] = pack2(src[lc * 4 + 2], src[lc * 4 + 3]);
      }
    }
    bb4 = make_float4(bbv[0], bbv[1], bbv[2], bbv[3]);
  }
  float4 cx0 = make_float4(0.f, 0.f, 0.f, 0.f);
  float4 cx1 = cx0;
  __syncthreads();

  // ---- encoder: 48 steps ----
  for (int t = 0; t < TT; t++) {
    if (half == 0) {
      const float* xt0 = x + ((size_t)b0 * TT + t) * (NNODE * INF);
      const float* xt1 = x + ((size_t)b1 * TT + t) * (NNODE * INF);
      float v0 = xt0[r * INF + j8];
      float v1 = xt1[r * INF + j8];
      *reinterpret_cast<p2*>(&s.xbufs[0][r][2 * j8]) = pack2(v0, v0);
      *reinterpret_cast<p2*>(&s.xbufs[1][r][2 * j8]) = pack2(v1, v1);
      if (j8 < 3) {
        float u0 = xt0[r * INF + j8 + 8];
        float u1 = xt1[r * INF + j8 + 8];
        *reinterpret_cast<p2*>(&s.xbufs[0][r][2 * (j8 + 8)]) = pack2(u0, u0);
        *reinterpret_cast<p2*>(&s.xbufs[1][r][2 * (j8 + 8)]) = pack2(u1, u1);
      }
    }
    __syncthreads();
    step2(s, wk, bb4, zoff, cx0, cx1, half, r, j8, ca, colbase, lane);
  }

  // ---- decoder: 48 steps ----
  for (int f = 0; f < FUT; f++) {
    step2(s, wk, bb4, zoff, cx0, cx1, half, r, j8, ca, colbase, lane);
    // h1 = relu(hx @ W_d1 + b_d1); batch = half, 4 cols at 4*j8
    d1mm(&s.zbuf[half][r][64], &s.Wd1[0][0], s.bd1, &s.h1[half][r][0],
         4 * j8);
    __syncthreads();
    // res = h1 @ W_d2 + b_d2 ; pred += res ; emit (both batches)
    if (tid < 192) {
      int rr = tid / 6, d = tid - rr * 6;
      float acc0 = s.bd2[d], acc1 = s.bd2[d];
#pragma unroll
      for (int k = 0; k < 32; k++) {
        float wv = s.Wd2[k][d];
        acc0 += s.h1[0][rr][k] * wv;
        acc1 += s.h1[1][rr][k] * wv;
      }
      float p0 = s.xbufs[0][rr][2 * d] + acc0;
      float p1 = s.xbufs[1][rr][2 * d] + acc1;
      *reinterpret_cast<p2*>(&s.xbufs[0][rr][2 * d]) = pack2(p0, p0);
      *reinterpret_cast<p2*>(&s.xbufs[1][rr][2 * d]) = pack2(p1, p1);
      out[(((size_t)b0 * FUT + f) * NNODE + rr) * 6 + d] = p0;
      out[(((size_t)b1 * FUT + f) * NNODE + rr) * 6 + d] = p1;
    }
    __syncthreads();
  }
}

extern "C" void kernel_launch(void* const* d_in, const int* in_sizes, int n_in,
                              void* d_out, int out_size) {
  const float* x    = (const float*)d_in[0];
  const float* adj  = (const float*)d_in[1];
  const float* Wenc = (const float*)d_in[2];
  const float* benc = (const float*)d_in[3];
  const float* Wg1  = (const float*)d_in[4];
  const float* bg1  = (const float*)d_in[5];
  const float* Wg2  = (const float*)d_in[6];
  const float* bg2  = (const float*)d_in[7];
  const float* Wih  = (const float*)d_in[8];
  const float* Whh  = (const float*)d_in[9];
  const float* bih  = (const float*)d_in[10];
  const float* bhh  = (const float*)d_in[11];
  const float* Wd1  = (const float*)d_in[12];
  const float* bd1  = (const float*)d_in[13];
  const float* Wd2  = (const float*)d_in[14];
  const float* bd2  = (const float*)d_in[15];
  float* out = (float*)d_out;

  int B = in_sizes[0] / (TT * NNODE * INF);
  int nblk = (B + 1) / 2;

  cudaFuncSetAttribute(stgnn_kernel,
                       cudaFuncAttributeMaxDynamicSharedMemorySize,
                       (int)sizeof(Smem));
  stgnn_kernel<<<nblk, NT, sizeof(Smem)>>>(x, adj, Wenc, benc, Wg1, bg1, Wg2,
                                           bg2, Wih, Whh, bih, bhh, Wd1, bd1,
                                           Wd2, bd2, out, B);
}

// round 16
// speedup vs baseline: 2.1058x; 1.9469x over previous
#include <cuda_runtime.h>

#define NT 256          // threads per CTA
#define TT 48
#define FUT 48
#define NNODE 32
#define INF 11
#define LDA 68          // normal activation row stride (floats)
#define LDZ 132         // zbuf row stride: [xf(64) | hx(64)] + pad
#define LDGR 260        // padded g row stride (floats)

typedef unsigned long long p2;

__device__ __forceinline__ p2 ffma2p(p2 a, p2 b, p2 c) {
  p2 d;
  asm("fma.rn.f32x2 %0, %1, %2, %3;" : "=l"(d) : "l"(a), "l"(b), "l"(c));
  return d;
}
__device__ __forceinline__ p2 pack2(float lo, float hi) {
  p2 d;
  asm("mov.b64 %0, {%1, %2};" : "=l"(d) : "f"(lo), "f"(hi));
  return d;
}
__device__ __forceinline__ float2 up2(p2 a) {
  float2 f;
  asm("mov.b64 {%0, %1}, %2;" : "=f"(f.x), "=f"(f.y) : "l"(a));
  return f;
}
__device__ __forceinline__ float hadd2(p2 a) {
  float2 f = up2(a);
  return f.x + f.y;
}

// HW tanh (sm_75+): 1 MUFU-class op, max rel err ~2^-11.
__device__ __forceinline__ float tanhap(float x) {
  float y;
  asm("tanh.approx.f32 %0, %1;" : "=f"(y) : "f"(x));
  return y;
}
__device__ __forceinline__ float sigf(float x) {
  return fmaf(0.5f, tanhap(0.5f * x), 0.5f);
}
__device__ __forceinline__ float tanh_f(float x) { return tanhap(x); }

struct __align__(16) Smem {
  float Wenc[12][64];      // row 11 zero-padded
  float Wg1[64][64];
  float Wg2[64][64];
  float Wd1[64][32];
  float Wd2[32][8];
  float benc[64];
  float bg1[64];
  float bg2[64];
  float bd1[32];
  float bd2[8];
  float Ahat2[32][68];     // SPLAT pairs of normalized adjacency rows
  float dvec[32];
  float xbufs[2][32][24];  // SPLAT input frame (12 k, k=11 stays zero)
  float act0[2][32][LDA];  // enc / tmp2
  float act1[2][32][LDA];  // tmp
  float zbuf[2][32][LDZ];  // [xf | hx] per row (LSTM z-stream)
  float g[2][32][LDGR];    // LSTM pre-activations
  float h1[2][32][36];     // decoder hidden
};

__device__ __forceinline__ void st4(float* p, p2 a0, p2 a1, bool relu) {
  float2 f0 = up2(a0), f1 = up2(a1);
  float4 o;
  o.x = relu ? fmaxf(f0.x, 0.f) : f0.x;
  o.y = relu ? fmaxf(f0.y, 0.f) : f0.y;
  o.z = relu ? fmaxf(f1.x, 0.f) : f1.x;
  o.w = relu ? fmaxf(f1.y, 0.f) : f1.y;
  *reinterpret_cast<float4*>(p) = o;
}

// Two-batch GEMM, scalar-A broadcast loads (R7-exact datapath).
// Output cols {4j..4j+3} (+TWOBLK {32+4j..}).
template<int K, int LDW, bool BIAS, bool RELU, bool TWOBLK>
__device__ __forceinline__ void rowmm2x2(const float* __restrict__ A0,
                                         const float* __restrict__ A1,
                                         const float* __restrict__ W,
                                         const float* __restrict__ bias,
                                         float* __restrict__ out0,
                                         float* __restrict__ out1, int j) {
  const int ca = 4 * j;
  const int cb = 32 + 4 * j;
  p2 x0, x1, x2, x3, y0, y1, y2, y3;
  if (BIAS) {
    ulonglong2 b0 = *reinterpret_cast<const ulonglong2*>(bias + ca);
    x0 = b0.x; x1 = b0.y; y0 = b0.x; y1 = b0.y;
    if (TWOBLK) {
      ulonglong2 b1 = *reinterpret_cast<const ulonglong2*>(bias + cb);
      x2 = b1.x; x3 = b1.y; y2 = b1.x; y3 = b1.y;
    } else { x2 = x3 = y2 = y3 = 0ull; }
  } else {
    x0 = x1 = x2 = x3 = y0 = y1 = y2 = y3 = 0ull;
  }
#pragma unroll
  for (int k = 0; k < K; k++) {
    float av0 = A0[k], av1 = A1[k];
    p2 aa0 = pack2(av0, av0);
    p2 aa1 = pack2(av1, av1);
    ulonglong2 w0 = *reinterpret_cast<const ulonglong2*>(W + k * LDW + ca);
    x0 = ffma2p(aa0, w0.x, x0);
    x1 = ffma2p(aa0, w0.y, x1);
    y0 = ffma2p(aa1, w0.x, y0);
    y1 = ffma2p(aa1, w0.y, y1);
    if (TWOBLK) {
      ulonglong2 w1 = *reinterpret_cast<const ulonglong2*>(W + k * LDW + cb);
      x2 = ffma2p(aa0, w1.x, x2);
      x3 = ffma2p(aa0, w1.y, x3);
      y2 = ffma2p(aa1, w1.x, y2);
      y3 = ffma2p(aa1, w1.y, y3);
    }
  }
  st4(out0 + ca, x0, x1, RELU);
  st4(out1 + ca, y0, y1, RELU);
  if (TWOBLK) {
    st4(out0 + cb, x2, x3, RELU);
    st4(out1 + cb, y2, y3, RELU);
  }
}

// enc GEMM: A = SPLAT xbufs rows (K=12 padded), 8 output cols, relu.
__device__ __forceinline__ void encmm(const float* __restrict__ As0,
                                      const float* __restrict__ As1,
                                      const float* __restrict__ W,
                                      const float* __restrict__ bias,
                                      float* __restrict__ out0,
                                      float* __restrict__ out1, int j) {
  const int ca = 4 * j;
  const int cb = 32 + 4 * j;
  ulonglong2 b0 = *reinterpret_cast<const ulonglong2*>(bias + ca);
  ulonglong2 b1 = *reinterpret_cast<const ulonglong2*>(bias + cb);
  p2 x0 = b0.x, x1 = b0.y, x2 = b1.x, x3 = b1.y;
  p2 y0 = b0.x, y1 = b0.y, y2 = b1.x, y3 = b1.y;
#pragma unroll
  for (int t = 0; t < 3; t++) {
    ulonglong2 aA = *reinterpret_cast<const ulonglong2*>(As0 + 8 * t);
    ulonglong2 aB = *reinterpret_cast<const ulonglong2*>(As0 + 8 * t + 4);
    ulonglong2 cA = *reinterpret_cast<const ulonglong2*>(As1 + 8 * t);
    ulonglong2 cB = *reinterpret_cast<const ulonglong2*>(As1 + 8 * t + 4);
    p2 sp0[4] = {aA.x, aA.y, aB.x, aB.y};
    p2 sp1[4] = {cA.x, cA.y, cB.x, cB.y};
#pragma unroll
    for (int q = 0; q < 4; q++) {
      const float* wr = W + (4 * t + q) * 64;
      ulonglong2 w0 = *reinterpret_cast<const ulonglong2*>(wr + ca);
      ulonglong2 w1 = *reinterpret_cast<const ulonglong2*>(wr + cb);
      x0 = ffma2p(sp0[q], w0.x, x0);
      x1 = ffma2p(sp0[q], w0.y, x1);
      x2 = ffma2p(sp0[q], w1.x, x2);
      x3 = ffma2p(sp0[q], w1.y, x3);
      y0 = ffma2p(sp1[q], w0.x, y0);
      y1 = ffma2p(sp1[q], w0.y, y1);
      y2 = ffma2p(sp1[q], w1.x, y2);
      y3 = ffma2p(sp1[q], w1.y, y3);
    }
  }
  st4(out0 + ca, x0, x1, true);
  st4(out0 + cb, x2, x3, true);
  st4(out1 + ca, y0, y1, true);
  st4(out1 + cb, y2, y3, true);
}

// Ahat GEMM: A = pre-splatted Ahat2 row (shared by both batches),
// W0/W1 = per-batch dynamic matrices (normal layout, LDA-strided). K=32.
__device__ __forceinline__ void ahatmm_x2(const float* __restrict__ A2,
                                          const float* __restrict__ W0,
                                          const float* __restrict__ W1,
                                          const float* __restrict__ bias,
                                          float* __restrict__ out0,
                                          float* __restrict__ out1, int j) {
  const int ca = 4 * j;
  const int cb = 32 + 4 * j;
  ulonglong2 b0 = *reinterpret_cast<const ulonglong2*>(bias + ca);
  ulonglong2 b1 = *reinterpret_cast<const ulonglong2*>(bias + cb);
  p2 x0 = b0.x, x1 = b0.y, x2 = b1.x, x3 = b1.y;
  p2 y0 = b0.x, y1 = b0.y, y2 = b1.x, y3 = b1.y;
#pragma unroll
  for (int t = 0; t < 8; t++) {
    ulonglong2 aA = *reinterpret_cast<const ulonglong2*>(A2 + 8 * t);
    ulonglong2 aB = *reinterpret_cast<const ulonglong2*>(A2 + 8 * t + 4);
    p2 sp[4] = {aA.x, aA.y, aB.x, aB.y};
#pragma unroll
    for (int q = 0; q < 4; q++) {
      const float* w0r = W0 + (4 * t + q) * LDA;
      const float* w1r = W1 + (4 * t + q) * LDA;
      ulonglong2 wa = *reinterpret_cast<const ulonglong2*>(w0r + ca);
      ulonglong2 wb = *reinterpret_cast<const ulonglong2*>(w0r + cb);
      x0 = ffma2p(sp[q], wa.x, x0);
      x1 = ffma2p(sp[q], wa.y, x1);
      x2 = ffma2p(sp[q], wb.x, x2);
      x3 = ffma2p(sp[q], wb.y, x3);
      ulonglong2 wc = *reinterpret_cast<const ulonglong2*>(w1r + ca);
      ulonglong2 wd = *reinterpret_cast<const ulonglong2*>(w1r + cb);
      y0 = ffma2p(sp[q], wc.x, y0);
      y1 = ffma2p(sp[q], wc.y, y1);
      y2 = ffma2p(sp[q], wd.x, y2);
      y3 = ffma2p(sp[q], wd.y, y3);
    }
  }
  st4(out0 + ca, x0, x1, true);
  st4(out0 + cb, x2, x3, true);
  st4(out1 + ca, y0, y1, true);
  st4(out1 + cb, y2, y3, true);
}

// Full two-batch step: GCN (2 layers) + LSTM + gates. R7 barrier schedule.
// LSTM split (R7): lane = (kc = lane>>3, cg = lane&7); thread owns 4 gate
// columns (colbase..+3) x its 32-k quarter; wk register resident; shfl
// reduction over the 4 kc groups.
__device__ __forceinline__ void step2(Smem& s, const p2 wk[4][16],
                                      const float4& bb4, const int* zoff,
                                      float4& c00, float4& c01,
                                      float4& c10, float4& c11,
                                      int tid, int colbase, int lane) {
  const int r = tid >> 3;
  const int j = tid & 7;

  // enc = relu(x @ W_enc + b_enc) -> act0               (row-local consumer)
  encmm(&s.xbufs[0][r][0], &s.xbufs[1][r][0], &s.Wenc[0][0], s.benc,
        &s.act0[0][r][0], &s.act0[1][r][0], j);
  __syncwarp();
  // tmp = enc @ W_g1 -> act1                            (all-to-all consumer)
  rowmm2x2<64, 64, false, false, true>(&s.act0[0][r][0], &s.act0[1][r][0],
                                       &s.Wg1[0][0], nullptr,
                                       &s.act1[0][r][0], &s.act1[1][r][0], j);
  __syncthreads();
  // s1 = relu(Ahat @ tmp + b_g1) -> zbuf[0..64)         (row-local consumer)
  ahatmm_x2(&s.Ahat2[r][0], &s.act1[0][0][0], &s.act1[1][0][0], s.bg1,
            &s.zbuf[0][r][0], &s.zbuf[1][r][0], j);
  __syncwarp();
  // tmp2 = s1 @ W_g2 -> act0                            (all-to-all consumer)
  rowmm2x2<64, 64, false, false, true>(&s.zbuf[0][r][0], &s.zbuf[1][r][0],
                                       &s.Wg2[0][0], nullptr,
                                       &s.act0[0][r][0], &s.act0[1][r][0], j);
  __syncthreads();
  // xf = relu(Ahat @ tmp2 + b_g2) -> zbuf[0..64)        (LSTM z-stream)
  ahatmm_x2(&s.Ahat2[r][0], &s.act0[0][0][0], &s.act0[1][0][0], s.bg2,
            &s.zbuf[0][r][0], &s.zbuf[1][r][0], j);
  __syncthreads();

  // LSTM both batches: g[bat][row][c] = bias + z[bat][row] . W[:,c]
#pragma unroll 2
  for (int rr = 0; rr < 32; rr++) {
    const float* zr0 = &s.zbuf[0][rr][0];
    const float* zr1 = &s.zbuf[1][rr][0];
    p2 a0 = 0ull, a1 = 0ull, a2 = 0ull, a3 = 0ull;
    p2 e0 = 0ull, e1 = 0ull, e2 = 0ull, e3 = 0ull;
#pragma unroll
    for (int i = 0; i < 8; i++) {
      ulonglong2 z0 = *reinterpret_cast<const ulonglong2*>(zr0 + zoff[i]);
      ulonglong2 z1 = *reinterpret_cast<const ulonglong2*>(zr1 + zoff[i]);
      p2 wlo0 = wk[0][2 * i], whi0 = wk[0][2 * i + 1];
      p2 wlo1 = wk[1][2 * i], whi1 = wk[1][2 * i + 1];
      p2 wlo2 = wk[2][2 * i], whi2 = wk[2][2 * i + 1];
      p2 wlo3 = wk[3][2 * i], whi3 = wk[3][2 * i + 1];
      a0 = ffma2p(z0.x, wlo0, a0); a0 = ffma2p(z0.y, whi0, a0);
      a1 = ffma2p(z0.x, wlo1, a1); a1 = ffma2p(z0.y, whi1, a1);
      a2 = ffma2p(z0.x, wlo2, a2); a2 = ffma2p(z0.y, whi2, a2);
      a3 = ffma2p(z0.x, wlo3, a3); a3 = ffma2p(z0.y, whi3, a3);
      e0 = ffma2p(z1.x, wlo0, e0); e0 = ffma2p(z1.y, whi0, e0);
      e1 = ffma2p(z1.x, wlo1, e1); e1 = ffma2p(z1.y, whi1, e1);
      e2 = ffma2p(z1.x, wlo2, e2); e2 = ffma2p(z1.y, whi2, e2);
      e3 = ffma2p(z1.x, wlo3, e3); e3 = ffma2p(z1.y, whi3, e3);
    }
    float s0 = hadd2(a0), s1v = hadd2(a1), s2 = hadd2(a2), s3 = hadd2(a3);
    float t0 = hadd2(e0), t1 = hadd2(e1), t2 = hadd2(e2), t3 = hadd2(e3);
    s0 += __shfl_xor_sync(0xffffffffu, s0, 8);
    s1v += __shfl_xor_sync(0xffffffffu, s1v, 8);
    s2 += __shfl_xor_sync(0xffffffffu, s2, 8);
    s3 += __shfl_xor_sync(0xffffffffu, s3, 8);
    t0 += __shfl_xor_sync(0xffffffffu, t0, 8);
    t1 += __shfl_xor_sync(0xffffffffu, t1, 8);
    t2 += __shfl_xor_sync(0xffffffffu, t2, 8);
    t3 += __shfl_xor_sync(0xffffffffu, t3, 8);
    s0 += __shfl_xor_sync(0xffffffffu, s0, 16);
    s1v += __shfl_xor_sync(0xffffffffu, s1v, 16);
    s2 += __shfl_xor_sync(0xffffffffu, s2, 16);
    s3 += __shfl_xor_sync(0xffffffffu, s3, 16);
    t0 += __shfl_xor_sync(0xffffffffu, t0, 16);
    t1 += __shfl_xor_sync(0xffffffffu, t1, 16);
    t2 += __shfl_xor_sync(0xffffffffu, t2, 16);
    t3 += __shfl_xor_sync(0xffffffffu, t3, 16);
    if (lane < 8) {
      float4 o0, o1;
      o0.x = s0 + bb4.x; o0.y = s1v + bb4.y;
      o0.z = s2 + bb4.z; o0.w = s3 + bb4.w;
      o1.x = t0 + bb4.x; o1.y = t1 + bb4.y;
      o1.z = t2 + bb4.z; o1.w = t3 + bb4.w;
      *reinterpret_cast<float4*>(&s.g[0][rr][colbase]) = o0;
      *reinterpret_cast<float4*>(&s.g[1][rr][colbase]) = o1;
    }
  }
  __syncthreads();

  // gate nonlinearity + state update; hx -> zbuf[64+base] (normal)
#pragma unroll
  for (int sel = 0; sel < 4; sel++) {
    int bat = sel >> 1;
    int h4 = sel & 1;
    int base = h4 * 32 + 4 * j;
    float4 gi = *reinterpret_cast<const float4*>(&s.g[bat][r][base]);
    float4 gf = *reinterpret_cast<const float4*>(&s.g[bat][r][64 + base]);
    float4 gg = *reinterpret_cast<const float4*>(&s.g[bat][r][128 + base]);
    float4 go = *reinterpret_cast<const float4*>(&s.g[bat][r][192 + base]);
    float4 cc = (sel == 0) ? c00 : (sel == 1) ? c01 : (sel == 2) ? c10 : c11;
    float4 cn, hn;
    cn.x = sigf(gf.x) * cc.x + sigf(gi.x) * tanh_f(gg.x);
    cn.y = sigf(gf.y) * cc.y + sigf(gi.y) * tanh_f(gg.y);
    cn.z = sigf(gf.z) * cc.z + sigf(gi.z) * tanh_f(gg.z);
    cn.w = sigf(gf.w) * cc.w + sigf(gi.w) * tanh_f(gg.w);
    hn.x = sigf(go.x) * tanh_f(cn.x);
    hn.y = sigf(go.y) * tanh_f(cn.y);
    hn.z = sigf(go.z) * tanh_f(cn.z);
    hn.w = sigf(go.w) * tanh_f(cn.w);
    if (sel == 0) c00 = cn; else if (sel == 1) c01 = cn;
    else if (sel == 2) c10 = cn; else c11 = cn;
    *reinterpret_cast<float4*>(&s.zbuf[bat][r][64 + base]) = hn;
  }
  __syncwarp();
}

__global__ void __launch_bounds__(NT, 1)
stgnn_kernel(const float* __restrict__ x, const float* __restrict__ adj,
             const float* __restrict__ Wenc_g, const float* __restrict__ benc_g,
             const float* __restrict__ Wg1_g, const float* __restrict__ bg1_g,
             const float* __restrict__ Wg2_g, const float* __restrict__ bg2_g,
             const float* __restrict__ Wih_g, const float* __restrict__ Whh_g,
             const float* __restrict__ bih_g, const float* __restrict__ bhh_g,
             const float* __restrict__ Wd1_g, const float* __restrict__ bd1_g,
             const float* __restrict__ Wd2_g, const float* __restrict__ bd2_g,
             float* __restrict__ out, int B) {
  extern __shared__ __align__(16) unsigned char smem_raw[];
  Smem& s = *reinterpret_cast<Smem*>(smem_raw);
  const int tid = threadIdx.x;
  const int b0 = 2 * blockIdx.x;
  const int b1 = min(b0 + 1, B - 1);   // clamp for odd B (duplicate work)
  const int r = tid >> 3;
  const int j = tid & 7;
  const int w = tid >> 5;
  const int lane = tid & 31;
  const int kc = lane >> 3;
  const int cg = lane & 7;
  const int colbase = 32 * w + 4 * cg;

  // ---- one-time per-CTA setup ----
  for (int i = tid; i < 12 * 64; i += NT) {
    int k = i >> 6, c = i & 63;
    (&s.Wenc[0][0])[i] = (k < INF) ? Wenc_g[k * 64 + c] : 0.f;
  }
  for (int i = tid; i < 64 * 64; i += NT) (&s.Wg1[0][0])[i] = Wg1_g[i];
  for (int i = tid; i < 64 * 64; i += NT) (&s.Wg2[0][0])[i] = Wg2_g[i];
  for (int i = tid; i < 64 * 32; i += NT) (&s.Wd1[0][0])[i] = Wd1_g[i];
  if (tid < 192) s.Wd2[tid / 6][tid % 6] = Wd2_g[tid];
  if (tid < 64) {
    s.benc[tid] = benc_g[tid];
    s.bg1[tid] = bg1_g[tid];
    s.bg2[tid] = bg2_g[tid];
  }
  if (tid < 32) s.bd1[tid] = bd1_g[tid];
  if (tid < 6) s.bd2[tid] = bd2_g[tid];
  if (tid < 32) {
    float sum = 0.f;
    for (int jj = 0; jj < 32; jj++)
      sum += (jj == tid) ? 1.f : adj[tid * 32 + jj];
    s.dvec[tid] = rsqrtf(fmaxf(sum, 1.f));
  }
  for (int i = tid; i < 2 * 32 * LDZ; i += NT) (&s.zbuf[0][0][0])[i] = 0.f;
  for (int i = tid; i < 2 * 32 * 24; i += NT) (&s.xbufs[0][0][0])[i] = 0.f;
  __syncthreads();
  for (int i = tid; i < 32 * 32; i += NT) {
    int ii = i >> 5, jj = i & 31;
    float a = (ii == jj) ? 1.f : adj[i];
    float v = s.dvec[ii] * a * s.dvec[jj];
    s.Ahat2[ii][2 * jj] = v;
    s.Ahat2[ii][2 * jj + 1] = v;
  }

  // LSTM weights: 4 cols x 32-k quarter (rotation baked in), shared by both
  // batches. Full k-vector for col c: k<64 -> W_ih[c][k], else W_hh[c][k-64].
  p2 wk[4][16];
  float4 bb4;
  int zoff[8];
#pragma unroll
  for (int i = 0; i < 8; i++) {
    int lc = (i + 2 * kc) & 7;
    zoff[i] = kc * 32 + lc * 4;
  }
  {
    const float* base =
        (kc < 2) ? (Wih_g + (size_t)kc * 32) : (Whh_g + (size_t)(kc - 2) * 32);
    float bbv[4];
#pragma unroll
    for (int cc = 0; cc < 4; cc++) {
      int c = colbase + cc;
      bbv[cc] = bih_g[c] + bhh_g[c];
      const float* src = base + (size_t)c * 64;
#pragma unroll
      for (int i = 0; i < 8; i++) {
        int lc = (i + 2 * kc) & 7;
        wk[cc][2 * i]     = pack2(src[lc * 4],     src[lc * 4 + 1]);
        wk[cc][2 * i + 1] = pack2(src[lc * 4 + 2], src[lc * 4 + 3]);
      }
    }
    bb4 = make_float4(bbv[0], bbv[1], bbv[2], bbv[3]);
  }
  float4 c00 = make_float4(0.f, 0.f, 0.f, 0.f), c01 = c00;
  float4 c10 = c00, c11 = c00;
  __syncthreads();

  // ---- encoder: 48 steps ----
  for (int t = 0; t < TT; t++) {
    const float* xt0 = x + ((size_t)b0 * TT + t) * (NNODE * INF);
    const float* xt1 = x + ((size_t)b1 * TT + t) * (NNODE * INF);
    float v0 = xt0[r * INF + j];
    float v1 = xt1[r * INF + j];
    *reinterpret_cast<p2*>(&s.xbufs[0][r][2 * j]) = pack2(v0, v0);
    *reinterpret_cast<p2*>(&s.xbufs[1][r][2 * j]) = pack2(v1, v1);
    if (j < 3) {
      float u0 = xt0[r * INF + j + 8];
      float u1 = xt1[r * INF + j + 8];
      *reinterpret_cast<p2*>(&s.xbufs[0][r][2 * (j + 8)]) = pack2(u0, u0);
      *reinterpret_cast<p2*>(&s.xbufs[1][r][2 * (j + 8)]) = pack2(u1, u1);
    }
    __syncwarp();
    step2(s, wk, bb4, zoff, c00, c01, c10, c11, tid, colbase, lane);
  }

  // ---- decoder: 48 steps ----
  for (int f = 0; f < FUT; f++) {
    step2(s, wk, bb4, zoff, c00, c01, c10, c11, tid, colbase, lane);
    // h1 = relu(hx @ W_d1 + b_d1); hx row-local in zbuf[bat][r][64..128)
    rowmm2x2<64, 32, true, true, false>(&s.zbuf[0][r][64], &s.zbuf[1][r][64],
                                        &s.Wd1[0][0], s.bd1,
                                        &s.h1[0][r][0], &s.h1[1][r][0], j);
    __syncthreads();
    // res = h1 @ W_d2 + b_d2 ; pred += res ; emit (both batches)
    if (tid < 192) {
      int rr = tid / 6, d = tid - rr * 6;
      float acc0 = s.bd2[d], acc1 = s.bd2[d];
#pragma unroll
      for (int k = 0; k < 32; k++) {
        float wv = s.Wd2[k][d];
        acc0 += s.h1[0][rr][k] * wv;
        acc1 += s.h1[1][rr][k] * wv;
      }
      float p0 = s.xbufs[0][rr][2 * d] + acc0;
      float p1 = s.xbufs[1][rr][2 * d] + acc1;
      *reinterpret_cast<p2*>(&s.xbufs[0][rr][2 * d]) = pack2(p0, p0);
      *reinterpret_cast<p2*>(&s.xbufs[1][rr][2 * d]) = pack2(p1, p1);
      out[(((size_t)b0 * FUT + f) * NNODE + rr) * 6 + d] = p0;
      out[(((size_t)b1 * FUT + f) * NNODE + rr) * 6 + d] = p1;
    }
    __syncthreads();
  }
}

extern "C" void kernel_launch(void* const* d_in, const int* in_sizes, int n_in,
                              void* d_out, int out_size) {
  const float* x    = (const float*)d_in[0];
  const float* adj  = (const float*)d_in[1];
  const float* Wenc = (const float*)d_in[2];
  const float* benc = (const float*)d_in[3];
  const float* Wg1  = (const float*)d_in[4];
  const float* bg1  = (const float*)d_in[5];
  const float* Wg2  = (const float*)d_in[6];
  const float* bg2  = (const float*)d_in[7];
  const float* Wih  = (const float*)d_in[8];
  const float* Whh  = (const float*)d_in[9];
  const float* bih  = (const float*)d_in[10];
  const float* bhh  = (const float*)d_in[11];
  const float* Wd1  = (const float*)d_in[12];
  const float* bd1  = (const float*)d_in[13];
  const float* Wd2  = (const float*)d_in[14];
  const float* bd2  = (const float*)d_in[15];
  float* out = (float*)d_out;

  int B = in_sizes[0] / (TT * NNODE * INF);
  int nblk = (B + 1) / 2;

  cudaFuncSetAttribute(stgnn_kernel,
                       cudaFuncAttributeMaxDynamicSharedMemorySize,
                       (int)sizeof(Smem));
  stgnn_kernel<<<nblk, NT, sizeof(Smem)>>>(x, adj, Wenc, benc, Wg1, bg1, Wg2,
                                           bg2, Wih, Whh, bih, bhh, Wd1, bd1,
                                           Wd2, bd2, out, B);
}